// round 10
// baseline (speedup 1.0000x reference)
#include <cuda_runtime.h>
#include <math.h>

#define BB 128
#define SS 26
#define AA 5
#define PP 3380   /* 26*26*5 */
#define MM 30
#define TILE 256
#define NTILES 14 /* ceil(3380/256) */
#define CWF 16.0f
#define INV_IM (1.0f / 416.0f)
#define CWS (16.0f / 416.0f)
#define EPS_S (1e-9f / (416.0f * 416.0f))

#define N_PRED 10816000
#define N_TGT  19200
#define N_ANC  10

__device__ unsigned long long g_part[BB * NTILES * MM];
__device__ float  g_confp[BB * NTILES];
__device__ double g_bloc[BB];
__device__ double g_bconf[BB];
__device__ int    g_bctr[BB];  // zero at load; reset each run by batch-last block
__device__ int    g_gctr;      // zero at load; reset each run by global-last block

__device__ __forceinline__ float sigf(float x) {
    return 1.0f / (1.0f + __expf(-x));
}
// order-preserving float -> u32 (monotone for all non-NaN floats)
__device__ __forceinline__ unsigned int okey(float f) {
    unsigned int u = __float_as_uint(f);
    return (u & 0x80000000u) ? ~u : (u | 0x80000000u);
}
// saturating add: clamp(a+b, 0, 1). All scaled overlap extents are < 1,
// so this equals the reference's clip(a+b, 0). -INF/NaN flush to +0.
__device__ __forceinline__ float addsat(float a, float b) {
    float r;
    asm("add.rn.sat.f32 %0, %1, %2;" : "=f"(r) : "f"(a), "f"(b));
    return r;
}

__global__ __launch_bounds__(TILE, 8) void k_main(
    const float* __restrict__ pred,
    const float* __restrict__ tgt,
    const float* __restrict__ anc,
    float* __restrict__ out)
{
    __shared__ float4 sBox[TILE];          // scaled (x2, y2, -x1, -y1)
    __shared__ float  sArea[TILE];         // scaled area
    __shared__ float  sTgt[MM * 5];
    __shared__ unsigned long long sMerge[MM];
    __shared__ float  sConf[TILE / 32];

    const int tid  = threadIdx.x;
    const int lane = tid & 31;
    const int warp = tid >> 5;
    const int b    = blockIdx.x / NTILES;
    const int tile = blockIdx.x % NTILES;
    const int nrec = min(TILE, PP - tile * TILE);   // 256, or 52 on last tile
    const float INF = __int_as_float(0x7f800000);

    if (tid < MM * 5) sTgt[tid] = tgt[b * MM * 5 + tid];
    if (tid < MM) sMerge[tid] = 0ull;

    // ---- decode one prediction per thread (scaled by 1/416) ----
    float t1 = 0.f, t2 = 0.f;
    if (tid < nrec) {
        const int p = tile * TILE + tid;
        const float* pv = pred + ((size_t)b * PP + p) * 25;
        float v0 = __ldg(pv + 0), v1 = __ldg(pv + 1), v2 = __ldg(pv + 2);
        float v3 = __ldg(pv + 3), v4 = __ldg(pv + 4);
        int a   = p % AA;
        int rem = p / AA;
        int jc  = rem % SS;
        int ir  = rem / SS;
        float bw = __expf(0.5f * sigf(v2)) * __ldg(&anc[2 * a])     * CWS;
        float bh = __expf(0.5f * sigf(v3)) * __ldg(&anc[2 * a + 1]) * CWS;
        float bx = (sigf(v0) + (float)jc) * CWS;
        float by = (sigf(v1) + (float)ir) * CWS;
        float hw = 0.5f * bw, hh = 0.5f * bh;
        sBox[tid]  = make_float4(bx + hw, by + hh, hw - bx, hh - by);
        sArea[tid] = bw * bh;
        float pc = sigf(v4);
        t1 = (pc - 1.f) * (pc - 1.f);
        t2 = 0.5f * pc * pc;
    }
    __syncthreads();

    // ---- GT box per lane (lane = annotation m), scaled ----
    float gx2, gy2, ngx1, ngy1, s;
    {
        bool v = false;
        float x1 = 0.f, y1 = 0.f, w = 0.f, h = 0.f;
        if (lane < MM) {
            x1 = sTgt[lane * 5 + 0]; y1 = sTgt[lane * 5 + 1];
            w  = sTgt[lane * 5 + 2]; h  = sTgt[lane * 5 + 3];
            v  = (sTgt[lane * 5 + 4] == 1.0f);
        }
        float gxc = (x1 + 0.5f * w) * INV_IM;
        float gyc = (y1 + 0.5f * h) * INV_IM;
        float gw  = (w - x1) * INV_IM;    // faithful to source (scaled)
        float gh  = (h * y1) * INV_IM;    // faithful to source (scaled)
        float gx1 = gxc - 0.5f * gw; gx2 = gxc + 0.5f * gw;
        float gy1 = gyc - 0.5f * gh; gy2 = gyc + 0.5f * gh;
        s = gw * gh + EPS_S;
        if (!v) { gx1 = INF; gx2 = -INF; gy1 = INF; gy2 = -INF; s = EPS_S; }
        ngx1 = -gx1; ngy1 = -gy1;
    }

    // ---- IoU sweep: warp handles its 32 preds, lane = m ----
    // dx = sat(min(gx2,px2) + min(-gx1,-px1)) clamps [0,1]; extents < 1 always.
    // Within a lane, IEEE '>' keeps first index on +0/-0 ties (argmax parity);
    // -0.0 canonicalized once at key-pack time for the cross-warp merge.
    unsigned mask = 0;
    float best = -INF;
    int   bestj = 0;
    const int base = warp * 32;
    const int pw = tile * TILE + base;
    int jcnt = nrec - base;
    if (jcnt > 32) jcnt = 32;
    if (jcnt < 0)  jcnt = 0;

    if (jcnt == 32) {
        #pragma unroll
        for (int j = 0; j < 32; ++j) {
            float4 bx = sBox[base + j];       // broadcast LDS.128
            float  ap = sArea[base + j];      // broadcast LDS.32
            float dx = addsat(fminf(gx2, bx.x), fminf(ngx1, bx.z));
            float dy = addsat(fminf(gy2, bx.y), fminf(ngy1, bx.w));
            float inter = dx * dy;
            float den = fmaf(-dx, dy, s + ap);
            float iou = inter * __frcp_rn(den);
            if (iou > 0.6f) mask |= (1u << j);
            if (iou > best) { best = iou; bestj = j; }
        }
    } else {
        for (int j = 0; j < jcnt; ++j) {
            float4 bx = sBox[base + j];
            float  ap = sArea[base + j];
            float dx = addsat(fminf(gx2, bx.x), fminf(ngx1, bx.z));
            float dy = addsat(fminf(gy2, bx.y), fminf(ngy1, bx.w));
            float inter = dx * dy;
            float den = fmaf(-dx, dy, s + ap);
            float iou = inter * __frcp_rn(den);
            if (iou > 0.6f) mask |= (1u << j);
            if (iou > best) { best = iou; bestj = j; }
        }
    }
    unsigned objw = __reduce_or_sync(0xFFFFFFFFu, mask);  // bit j = obj(pred pw+j)
    bool myobj = (objw >> lane) & 1u;

    if (lane < MM) {
        if (__float_as_uint(best) == 0x80000000u) best = 0.0f;  // -0 -> +0
        unsigned long long pk =
            ((unsigned long long)okey(best) << 32) | (unsigned int)(~(pw + bestj));
        atomicMax(&sMerge[lane], pk);
    }

    // ---- conf partial reduce (fixed order -> deterministic) ----
    float acc = (tid < nrec) ? (myobj ? t1 : t2) : 0.f;
    #pragma unroll
    for (int o = 16; o; o >>= 1) acc += __shfl_down_sync(0xFFFFFFFFu, acc, o);
    if (lane == 0) sConf[warp] = acc;
    __syncthreads();

    // ---- warp 0 publishes this tile's results, then maybe runs the tail ----
    if (warp != 0) return;

    if (lane < MM) g_part[(size_t)blockIdx.x * MM + lane] = sMerge[lane];
    {
        float v = (lane < TILE / 32) ? sConf[lane] : 0.f;
        #pragma unroll
        for (int o = 4; o; o >>= 1) v += __shfl_down_sync(0xFFFFFFFFu, v, o);
        if (lane == 0) g_confp[blockIdx.x] = v;
    }
    __threadfence();
    __syncwarp();
    int cnt = 0;
    if (lane == 0) cnt = atomicAdd(&g_bctr[b], 1);
    cnt = __shfl_sync(0xFFFFFFFFu, cnt, 0);
    if (cnt != NTILES - 1) return;

    // ===== per-batch post (last-arriving tile-block of batch b) =====
    // Uses ORIGINAL unscaled formulas (CWF) — unaffected by IoU scaling.
    unsigned long long bk = 0ull;
    float x1 = 0.f, y1 = 0.f, w = 0.f, h = 0.f;
    bool valid = false;
    if (lane < MM) {
        x1 = sTgt[lane * 5 + 0]; y1 = sTgt[lane * 5 + 1];
        w  = sTgt[lane * 5 + 2]; h  = sTgt[lane * 5 + 3];
        valid = (sTgt[lane * 5 + 4] == 1.0f);
        #pragma unroll
        for (int k = 0; k < NTILES; ++k) {
            unsigned long long v = __ldcg(&g_part[((size_t)b * NTILES + k) * MM + lane]);
            if (v > bk) bk = v;
        }
    }
    int p = valid ? (int)(~(unsigned int)bk) : (0x10000 + lane);

    // scatter .set semantics: same flat index -> highest m (last write) wins
    unsigned grp = __match_any_sync(0xFFFFFFFFu, p);
    bool writer = valid && (lane == 31 - __clz(grp));

    float term = 0.f;
    if (writer) {
        int ra = p % AA, rw = (p / AA) % SS, rh = p / (AA * SS);
        float gxc = x1 + 0.5f * w;
        float gyc = y1 + 0.5f * h;
        float vx = (gxc - (float)rw * CWF) / CWF;
        float vy = (gyc - (float)rh * CWF) / CWF;
        float vw_ = logf((w / CWF) / __ldg(&anc[2 * ra]));
        float vh_ = logf((h / CWF) / __ldg(&anc[2 * ra + 1]));
        const float* pv = pred + ((size_t)b * PP + p) * 25;
        float p0 = 1.f   / (1.f + expf(-pv[0]));
        float p1 = 1.f   / (1.f + expf(-pv[1]));
        float p2 = 0.5f  / (1.f + expf(-pv[2]));
        float p3 = 0.5f  / (1.f + expf(-pv[3]));
        float d0 = p0 - vx, d1 = p1 - vy, d2 = p2 - vw_, d3 = p3 - vh_;
        term = d0 * d0 + d1 * d1 + d2 * d2 + d3 * d3;
    }
    float cpart = (lane < NTILES) ? __ldcg(&g_confp[b * NTILES + lane]) : 0.f;
    #pragma unroll
    for (int o = 16; o; o >>= 1) {
        term  += __shfl_down_sync(0xFFFFFFFFu, term,  o);
        cpart += __shfl_down_sync(0xFFFFFFFFu, cpart, o);
    }

    int done = 0;
    if (lane == 0) {
        g_bctr[b] = 0;                 // reset for next launch
        g_bloc[b]  = (double)term;
        g_bconf[b] = (double)cpart;
        __threadfence();
        done = atomicAdd(&g_gctr, 1);
    }
    done = __shfl_sync(0xFFFFFFFFu, done, 0);
    if (done != BB - 1) return;

    // ===== global finalize (deterministic fixed-order reduce) =====
    double l = 0.0, c = 0.0;
    for (int i = lane; i < BB; i += 32) {
        l += __ldcg(&g_bloc[i]);
        c += __ldcg(&g_bconf[i]);
    }
    #pragma unroll
    for (int o = 16; o; o >>= 1) {
        l += __shfl_down_sync(0xFFFFFFFFu, l, o);
        c += __shfl_down_sync(0xFFFFFFFFu, c, o);
    }
    if (lane == 0) {
        double loc  = 5.0 * l / (double)BB;
        double conf = c / (double)BB;
        out[0] = (float)(loc + conf);
        out[1] = (float)loc;
        out[2] = (float)conf;
        g_gctr = 0;                    // reset for next launch
    }
}

extern "C" void kernel_launch(void* const* d_in, const int* in_sizes, int n_in,
                              void* d_out, int out_size)
{
    const float* pred = 0;
    const float* tgt  = 0;
    const float* anc  = 0;
    for (int i = 0; i < n_in; ++i) {
        if (in_sizes[i] == N_PRED)      pred = (const float*)d_in[i];
        else if (in_sizes[i] == N_TGT)  tgt  = (const float*)d_in[i];
        else if (in_sizes[i] == N_ANC)  anc  = (const float*)d_in[i];
    }
    float* out = (float*)d_out;

    k_main<<<BB * NTILES, TILE>>>(pred, tgt, anc, out);
}

// round 11
// speedup vs baseline: 1.0655x; 1.0655x over previous
#include <cuda_runtime.h>
#include <math.h>

#define BB 128
#define SS 26
#define AA 5
#define PP 3380   /* 26*26*5 */
#define MM 30
#define TILE 256
#define NTILES 14 /* ceil(3380/256) */
#define CWF 16.0f
#define INV_IM (1.0f / 416.0f)
#define CWS (16.0f / 416.0f)
#define EPS_S (1e-9f / (416.0f * 416.0f))

#define N_PRED 10816000
#define N_TGT  19200
#define N_ANC  10

__device__ unsigned long long g_part[BB * NTILES * MM];
__device__ float  g_confp[BB * NTILES];
__device__ double g_bloc[BB];
__device__ double g_bconf[BB];
__device__ int    g_bctr[BB];  // zero at load; reset each run by batch-last block
__device__ int    g_gctr;      // zero at load; reset each run by global-last block

__device__ __forceinline__ float sigf(float x) {
    return 1.0f / (1.0f + __expf(-x));
}
// order-preserving float -> u32 (monotone for all non-NaN floats)
__device__ __forceinline__ unsigned int okey(float f) {
    unsigned int u = __float_as_uint(f);
    return (u & 0x80000000u) ? ~u : (u | 0x80000000u);
}
// saturating add: clamp(a+b, 0, 1). All scaled overlap extents are < 1,
// so this equals the reference's clip(a+b, 0). -INF/NaN flush to +0.
__device__ __forceinline__ float addsat(float a, float b) {
    float r;
    asm("add.rn.sat.f32 %0, %1, %2;" : "=f"(r) : "f"(a), "f"(b));
    return r;
}

__global__ __launch_bounds__(TILE, 8) void k_main(
    const float* __restrict__ pred,
    const float* __restrict__ tgt,
    const float* __restrict__ anc,
    float* __restrict__ out)
{
    __shared__ float4 sBox[TILE];          // scaled (x2, y2, -x1, -y1)
    __shared__ float  sArea[TILE];         // scaled area
    __shared__ float  sTgt[MM * 5];
    __shared__ unsigned long long sMerge[MM];
    __shared__ float  sConf[TILE / 32];

    const int tid  = threadIdx.x;
    const int lane = tid & 31;
    const int warp = tid >> 5;
    const int b    = blockIdx.x / NTILES;
    const int tile = blockIdx.x % NTILES;
    const int nrec = min(TILE, PP - tile * TILE);   // 256, or 52 on last tile
    const float INF = __int_as_float(0x7f800000);

    if (tid < MM * 5) sTgt[tid] = tgt[b * MM * 5 + tid];
    if (tid < MM) sMerge[tid] = 0ull;

    // ---- decode one prediction per thread (scaled by 1/416) ----
    float t1 = 0.f, t2 = 0.f;
    if (tid < nrec) {
        const int p = tile * TILE + tid;
        const float* pv = pred + ((size_t)b * PP + p) * 25;
        float v0 = __ldg(pv + 0), v1 = __ldg(pv + 1), v2 = __ldg(pv + 2);
        float v3 = __ldg(pv + 3), v4 = __ldg(pv + 4);
        int a   = p % AA;
        int rem = p / AA;
        int jc  = rem % SS;
        int ir  = rem / SS;
        float bw = __expf(0.5f * sigf(v2)) * __ldg(&anc[2 * a])     * CWS;
        float bh = __expf(0.5f * sigf(v3)) * __ldg(&anc[2 * a + 1]) * CWS;
        float bx = (sigf(v0) + (float)jc) * CWS;
        float by = (sigf(v1) + (float)ir) * CWS;
        float hw = 0.5f * bw, hh = 0.5f * bh;
        sBox[tid]  = make_float4(bx + hw, by + hh, hw - bx, hh - by);
        sArea[tid] = bw * bh;
        float pc = sigf(v4);
        t1 = (pc - 1.f) * (pc - 1.f);
        t2 = 0.5f * pc * pc;
    }
    __syncthreads();

    // ---- GT box per lane (lane = annotation m), scaled ----
    float gx2, gy2, ngx1, ngy1, s;
    {
        bool v = false;
        float x1 = 0.f, y1 = 0.f, w = 0.f, h = 0.f;
        if (lane < MM) {
            x1 = sTgt[lane * 5 + 0]; y1 = sTgt[lane * 5 + 1];
            w  = sTgt[lane * 5 + 2]; h  = sTgt[lane * 5 + 3];
            v  = (sTgt[lane * 5 + 4] == 1.0f);
        }
        float gxc = (x1 + 0.5f * w) * INV_IM;
        float gyc = (y1 + 0.5f * h) * INV_IM;
        float gw  = (w - x1) * INV_IM;    // faithful to source (scaled)
        float gh  = (h * y1) * INV_IM;    // faithful to source (scaled)
        float gx1 = gxc - 0.5f * gw; gx2 = gxc + 0.5f * gw;
        float gy1 = gyc - 0.5f * gh; gy2 = gyc + 0.5f * gh;
        s = gw * gh + EPS_S;
        if (!v) { gx1 = INF; gx2 = -INF; gy1 = INF; gy2 = -INF; s = EPS_S; }
        ngx1 = -gx1; ngy1 = -gy1;
    }

    // ---- IoU sweep: warp handles its 32 preds, lane = m ----
    // dx = sat(min(gx2,px2) + min(-gx1,-px1)) clamps [0,1]; extents < 1 always.
    // Within a lane, IEEE '>' keeps first index on +0/-0 ties (argmax parity);
    // -0.0 canonicalized once at key-pack time for the cross-warp merge.
    unsigned mask = 0;
    float best = -INF;
    int   bestj = 0;
    const int base = warp * 32;
    const int pw = tile * TILE + base;
    int jcnt = nrec - base;
    if (jcnt > 32) jcnt = 32;
    if (jcnt < 0)  jcnt = 0;

    if (jcnt == 32) {
        #pragma unroll
        for (int j = 0; j < 32; ++j) {
            float4 bx = sBox[base + j];       // broadcast LDS.128
            float  ap = sArea[base + j];      // broadcast LDS.32
            float dx = addsat(fminf(gx2, bx.x), fminf(ngx1, bx.z));
            float dy = addsat(fminf(gy2, bx.y), fminf(ngy1, bx.w));
            float inter = dx * dy;
            float den = fmaf(-dx, dy, s + ap);
            float iou = __fdividef(inter, den);
            if (iou > 0.6f) mask |= (1u << j);
            if (iou > best) { best = iou; bestj = j; }
        }
    } else {
        for (int j = 0; j < jcnt; ++j) {
            float4 bx = sBox[base + j];
            float  ap = sArea[base + j];
            float dx = addsat(fminf(gx2, bx.x), fminf(ngx1, bx.z));
            float dy = addsat(fminf(gy2, bx.y), fminf(ngy1, bx.w));
            float inter = dx * dy;
            float den = fmaf(-dx, dy, s + ap);
            float iou = __fdividef(inter, den);
            if (iou > 0.6f) mask |= (1u << j);
            if (iou > best) { best = iou; bestj = j; }
        }
    }
    unsigned objw = __reduce_or_sync(0xFFFFFFFFu, mask);  // bit j = obj(pred pw+j)
    bool myobj = (objw >> lane) & 1u;

    if (lane < MM) {
        if (__float_as_uint(best) == 0x80000000u) best = 0.0f;  // -0 -> +0
        unsigned long long pk =
            ((unsigned long long)okey(best) << 32) | (unsigned int)(~(pw + bestj));
        atomicMax(&sMerge[lane], pk);
    }

    // ---- conf partial reduce (fixed order -> deterministic) ----
    float acc = (tid < nrec) ? (myobj ? t1 : t2) : 0.f;
    #pragma unroll
    for (int o = 16; o; o >>= 1) acc += __shfl_down_sync(0xFFFFFFFFu, acc, o);
    if (lane == 0) sConf[warp] = acc;
    __syncthreads();

    // ---- warp 0 publishes this tile's results, then maybe runs the tail ----
    if (warp != 0) return;

    if (lane < MM) g_part[(size_t)blockIdx.x * MM + lane] = sMerge[lane];
    {
        float v = (lane < TILE / 32) ? sConf[lane] : 0.f;
        #pragma unroll
        for (int o = 4; o; o >>= 1) v += __shfl_down_sync(0xFFFFFFFFu, v, o);
        if (lane == 0) g_confp[blockIdx.x] = v;
    }
    __threadfence();
    __syncwarp();
    int cnt = 0;
    if (lane == 0) cnt = atomicAdd(&g_bctr[b], 1);
    cnt = __shfl_sync(0xFFFFFFFFu, cnt, 0);
    if (cnt != NTILES - 1) return;

    // ===== per-batch post (last-arriving tile-block of batch b) =====
    // Uses ORIGINAL unscaled formulas (CWF) — unaffected by IoU scaling.
    unsigned long long bk = 0ull;
    float x1 = 0.f, y1 = 0.f, w = 0.f, h = 0.f;
    bool valid = false;
    if (lane < MM) {
        x1 = sTgt[lane * 5 + 0]; y1 = sTgt[lane * 5 + 1];
        w  = sTgt[lane * 5 + 2]; h  = sTgt[lane * 5 + 3];
        valid = (sTgt[lane * 5 + 4] == 1.0f);
        #pragma unroll
        for (int k = 0; k < NTILES; ++k) {
            unsigned long long v = __ldcg(&g_part[((size_t)b * NTILES + k) * MM + lane]);
            if (v > bk) bk = v;
        }
    }
    int p = valid ? (int)(~(unsigned int)bk) : (0x10000 + lane);

    // scatter .set semantics: same flat index -> highest m (last write) wins
    unsigned grp = __match_any_sync(0xFFFFFFFFu, p);
    bool writer = valid && (lane == 31 - __clz(grp));

    float term = 0.f;
    if (writer) {
        int ra = p % AA, rw = (p / AA) % SS, rh = p / (AA * SS);
        float gxc = x1 + 0.5f * w;
        float gyc = y1 + 0.5f * h;
        float vx = (gxc - (float)rw * CWF) / CWF;
        float vy = (gyc - (float)rh * CWF) / CWF;
        float vw_ = logf((w / CWF) / __ldg(&anc[2 * ra]));
        float vh_ = logf((h / CWF) / __ldg(&anc[2 * ra + 1]));
        const float* pv = pred + ((size_t)b * PP + p) * 25;
        float p0 = 1.f   / (1.f + expf(-pv[0]));
        float p1 = 1.f   / (1.f + expf(-pv[1]));
        float p2 = 0.5f  / (1.f + expf(-pv[2]));
        float p3 = 0.5f  / (1.f + expf(-pv[3]));
        float d0 = p0 - vx, d1 = p1 - vy, d2 = p2 - vw_, d3 = p3 - vh_;
        term = d0 * d0 + d1 * d1 + d2 * d2 + d3 * d3;
    }
    float cpart = (lane < NTILES) ? __ldcg(&g_confp[b * NTILES + lane]) : 0.f;
    #pragma unroll
    for (int o = 16; o; o >>= 1) {
        term  += __shfl_down_sync(0xFFFFFFFFu, term,  o);
        cpart += __shfl_down_sync(0xFFFFFFFFu, cpart, o);
    }

    int done = 0;
    if (lane == 0) {
        g_bctr[b] = 0;                 // reset for next launch
        g_bloc[b]  = (double)term;
        g_bconf[b] = (double)cpart;
        __threadfence();
        done = atomicAdd(&g_gctr, 1);
    }
    done = __shfl_sync(0xFFFFFFFFu, done, 0);
    if (done != BB - 1) return;

    // ===== global finalize (deterministic fixed-order reduce) =====
    double l = 0.0, c = 0.0;
    for (int i = lane; i < BB; i += 32) {
        l += __ldcg(&g_bloc[i]);
        c += __ldcg(&g_bconf[i]);
    }
    #pragma unroll
    for (int o = 16; o; o >>= 1) {
        l += __shfl_down_sync(0xFFFFFFFFu, l, o);
        c += __shfl_down_sync(0xFFFFFFFFu, c, o);
    }
    if (lane == 0) {
        double loc  = 5.0 * l / (double)BB;
        double conf = c / (double)BB;
        out[0] = (float)(loc + conf);
        out[1] = (float)loc;
        out[2] = (float)conf;
        g_gctr = 0;                    // reset for next launch
    }
}

extern "C" void kernel_launch(void* const* d_in, const int* in_sizes, int n_in,
                              void* d_out, int out_size)
{
    const float* pred = 0;
    const float* tgt  = 0;
    const float* anc  = 0;
    for (int i = 0; i < n_in; ++i) {
        if (in_sizes[i] == N_PRED)      pred = (const float*)d_in[i];
        else if (in_sizes[i] == N_TGT)  tgt  = (const float*)d_in[i];
        else if (in_sizes[i] == N_ANC)  anc  = (const float*)d_in[i];
    }
    float* out = (float*)d_out;

    k_main<<<BB * NTILES, TILE>>>(pred, tgt, anc, out);
}

// round 12
// speedup vs baseline: 1.0923x; 1.0252x over previous
#include <cuda_runtime.h>
#include <math.h>

#define BB 128
#define SS 26
#define AA 5
#define PP 3380   /* 26*26*5 */
#define MM 30
#define TILE 256
#define NTILES 14 /* ceil(3380/256) */
#define CWF 16.0f
#define INV_IM (1.0f / 416.0f)
#define CWS (16.0f / 416.0f)
#define EPS_S (1e-9f / (416.0f * 416.0f))

#define N_PRED 10816000
#define N_TGT  19200
#define N_ANC  10

__device__ unsigned long long g_part[BB * NTILES * MM];
__device__ float  g_confp[BB * NTILES];
__device__ double g_bloc[BB];
__device__ double g_bconf[BB];
__device__ int    g_bctr[BB];  // zero at load; reset each run by batch-last block
__device__ int    g_gctr;      // zero at load; reset each run by global-last block

__device__ __forceinline__ float sigf(float x) {
    return 1.0f / (1.0f + __expf(-x));
}
// order-preserving float -> u32 (monotone for all non-NaN floats)
__device__ __forceinline__ unsigned int okey(float f) {
    unsigned int u = __float_as_uint(f);
    return (u & 0x80000000u) ? ~u : (u | 0x80000000u);
}
// saturating add: clamp(a+b, 0, 1). All scaled overlap extents are < 1,
// so this equals the reference's clip(a+b, 0). -INF/NaN flush to +0.
__device__ __forceinline__ float addsat(float a, float b) {
    float r;
    asm("add.rn.sat.f32 %0, %1, %2;" : "=f"(r) : "f"(a), "f"(b));
    return r;
}

__global__ __launch_bounds__(TILE) void k_main(
    const float* __restrict__ pred,
    const float* __restrict__ tgt,
    const float* __restrict__ anc,
    float* __restrict__ out)
{
    __shared__ float4 sBox[TILE];          // scaled (x2, y2, -x1, -y1)
    __shared__ float  sArea[TILE];         // scaled area
    __shared__ float  sTgt[MM * 5];
    __shared__ unsigned long long sMerge[MM];
    __shared__ float  sConf[TILE / 32];

    const int tid  = threadIdx.x;
    const int lane = tid & 31;
    const int warp = tid >> 5;
    const int b    = blockIdx.x / NTILES;
    const int tile = blockIdx.x % NTILES;
    const int nrec = min(TILE, PP - tile * TILE);   // 256, or 52 on last tile
    const float INF = __int_as_float(0x7f800000);

    if (tid < MM * 5) sTgt[tid] = tgt[b * MM * 5 + tid];
    if (tid < MM) sMerge[tid] = 0ull;

    // ---- decode one prediction per thread (scaled by 1/416) ----
    float t1 = 0.f, t2 = 0.f;
    if (tid < nrec) {
        const int p = tile * TILE + tid;
        const float* pv = pred + ((size_t)b * PP + p) * 25;
        float v0 = __ldg(pv + 0), v1 = __ldg(pv + 1), v2 = __ldg(pv + 2);
        float v3 = __ldg(pv + 3), v4 = __ldg(pv + 4);
        int a   = p % AA;
        int rem = p / AA;
        int jc  = rem % SS;
        int ir  = rem / SS;
        float bw = __expf(0.5f * sigf(v2)) * __ldg(&anc[2 * a])     * CWS;
        float bh = __expf(0.5f * sigf(v3)) * __ldg(&anc[2 * a + 1]) * CWS;
        float bx = (sigf(v0) + (float)jc) * CWS;
        float by = (sigf(v1) + (float)ir) * CWS;
        float hw = 0.5f * bw, hh = 0.5f * bh;
        sBox[tid]  = make_float4(bx + hw, by + hh, hw - bx, hh - by);
        sArea[tid] = bw * bh;
        float pc = sigf(v4);
        t1 = (pc - 1.f) * (pc - 1.f);
        t2 = 0.5f * pc * pc;
    }
    __syncthreads();

    // ---- GT box per lane (lane = annotation m), scaled ----
    float gx2, gy2, ngx1, ngy1, s;
    {
        bool v = false;
        float x1 = 0.f, y1 = 0.f, w = 0.f, h = 0.f;
        if (lane < MM) {
            x1 = sTgt[lane * 5 + 0]; y1 = sTgt[lane * 5 + 1];
            w  = sTgt[lane * 5 + 2]; h  = sTgt[lane * 5 + 3];
            v  = (sTgt[lane * 5 + 4] == 1.0f);
        }
        float gxc = (x1 + 0.5f * w) * INV_IM;
        float gyc = (y1 + 0.5f * h) * INV_IM;
        float gw  = (w - x1) * INV_IM;    // faithful to source (scaled)
        float gh  = (h * y1) * INV_IM;    // faithful to source (scaled)
        float gx1 = gxc - 0.5f * gw; gx2 = gxc + 0.5f * gw;
        float gy1 = gyc - 0.5f * gh; gy2 = gyc + 0.5f * gh;
        s = gw * gh + EPS_S;
        if (!v) { gx1 = INF; gx2 = -INF; gy1 = INF; gy2 = -INF; s = EPS_S; }
        ngx1 = -gx1; ngy1 = -gy1;
    }

    // ---- IoU sweep: warp handles its 32 preds, lane = m ----
    // Two independent accumulator chains (even/odd j) halve the loop-carried
    // dependency depth. Each chain keeps its first index on ties; merging with
    // min-j on equality reproduces jnp.argmax first-index semantics exactly
    // (+0.0 == -0.0 compare equal -> tie -> min j).
    unsigned mask0 = 0, mask1 = 0;
    float best0 = -INF, best1 = -INF;
    int   bestj0 = 0, bestj1 = 1;
    const int base = warp * 32;
    const int pw = tile * TILE + base;
    int jcnt = nrec - base;
    if (jcnt > 32) jcnt = 32;
    if (jcnt < 0)  jcnt = 0;

    if (jcnt == 32) {
        #pragma unroll
        for (int j = 0; j < 32; j += 2) {
            float4 bxa = sBox[base + j];
            float  apa = sArea[base + j];
            float4 bxb = sBox[base + j + 1];
            float  apb = sArea[base + j + 1];

            float dxa = addsat(fminf(gx2, bxa.x), fminf(ngx1, bxa.z));
            float dya = addsat(fminf(gy2, bxa.y), fminf(ngy1, bxa.w));
            float dxb = addsat(fminf(gx2, bxb.x), fminf(ngx1, bxb.z));
            float dyb = addsat(fminf(gy2, bxb.y), fminf(ngy1, bxb.w));

            float ia = dxa * dya;
            float ib = dxb * dyb;
            float da = fmaf(-dxa, dya, s + apa);
            float db = fmaf(-dxb, dyb, s + apb);
            float ioua = __fdividef(ia, da);
            float ioub = __fdividef(ib, db);

            if (ioua > 0.6f) mask0 |= (1u << j);
            if (ioub > 0.6f) mask1 |= (2u << j);
            if (ioua > best0) { best0 = ioua; bestj0 = j; }
            if (ioub > best1) { best1 = ioub; bestj1 = j + 1; }
        }
    } else {
        for (int j = 0; j < jcnt; ++j) {
            float4 bx = sBox[base + j];
            float  ap = sArea[base + j];
            float dx = addsat(fminf(gx2, bx.x), fminf(ngx1, bx.z));
            float dy = addsat(fminf(gy2, bx.y), fminf(ngy1, bx.w));
            float inter = dx * dy;
            float den = fmaf(-dx, dy, s + ap);
            float iou = __fdividef(inter, den);
            if (iou > 0.6f) mask0 |= (1u << j);
            if (iou > best0) { best0 = iou; bestj0 = j; }
        }
    }
    // merge chains: strict > keeps chain0 on equality unless chain1 strictly
    // greater; on exact tie take min index (chain0 index < chain1 index iff
    // bestj0 < bestj1; both orders possible, so compare explicitly)
    float best;
    int   bestj;
    if (best1 > best0)       { best = best1; bestj = bestj1; }
    else if (best0 > best1)  { best = best0; bestj = bestj0; }
    else                     { best = best0; bestj = min(bestj0, bestj1); }

    unsigned objw = __reduce_or_sync(0xFFFFFFFFu, mask0 | mask1);
    bool myobj = (objw >> lane) & 1u;

    if (lane < MM) {
        if (__float_as_uint(best) == 0x80000000u) best = 0.0f;  // -0 -> +0
        unsigned long long pk =
            ((unsigned long long)okey(best) << 32) | (unsigned int)(~(pw + bestj));
        atomicMax(&sMerge[lane], pk);
    }

    // ---- conf partial reduce (fixed order -> deterministic) ----
    float acc = (tid < nrec) ? (myobj ? t1 : t2) : 0.f;
    #pragma unroll
    for (int o = 16; o; o >>= 1) acc += __shfl_down_sync(0xFFFFFFFFu, acc, o);
    if (lane == 0) sConf[warp] = acc;
    __syncthreads();

    // ---- warp 0 publishes this tile's results, then maybe runs the tail ----
    if (warp != 0) return;

    if (lane < MM) g_part[(size_t)blockIdx.x * MM + lane] = sMerge[lane];
    {
        float v = (lane < TILE / 32) ? sConf[lane] : 0.f;
        #pragma unroll
        for (int o = 4; o; o >>= 1) v += __shfl_down_sync(0xFFFFFFFFu, v, o);
        if (lane == 0) g_confp[blockIdx.x] = v;
    }
    __threadfence();
    __syncwarp();
    int cnt = 0;
    if (lane == 0) cnt = atomicAdd(&g_bctr[b], 1);
    cnt = __shfl_sync(0xFFFFFFFFu, cnt, 0);
    if (cnt != NTILES - 1) return;

    // ===== per-batch post (last-arriving tile-block of batch b) =====
    // Uses ORIGINAL unscaled formulas (CWF) — unaffected by IoU scaling.
    unsigned long long bk = 0ull;
    float x1 = 0.f, y1 = 0.f, w = 0.f, h = 0.f;
    bool valid = false;
    if (lane < MM) {
        x1 = sTgt[lane * 5 + 0]; y1 = sTgt[lane * 5 + 1];
        w  = sTgt[lane * 5 + 2]; h  = sTgt[lane * 5 + 3];
        valid = (sTgt[lane * 5 + 4] == 1.0f);
        #pragma unroll
        for (int k = 0; k < NTILES; ++k) {
            unsigned long long v = __ldcg(&g_part[((size_t)b * NTILES + k) * MM + lane]);
            if (v > bk) bk = v;
        }
    }
    int p = valid ? (int)(~(unsigned int)bk) : (0x10000 + lane);

    // scatter .set semantics: same flat index -> highest m (last write) wins
    unsigned grp = __match_any_sync(0xFFFFFFFFu, p);
    bool writer = valid && (lane == 31 - __clz(grp));

    float term = 0.f;
    if (writer) {
        int ra = p % AA, rw = (p / AA) % SS, rh = p / (AA * SS);
        float gxc = x1 + 0.5f * w;
        float gyc = y1 + 0.5f * h;
        float vx = (gxc - (float)rw * CWF) / CWF;
        float vy = (gyc - (float)rh * CWF) / CWF;
        float vw_ = logf((w / CWF) / __ldg(&anc[2 * ra]));
        float vh_ = logf((h / CWF) / __ldg(&anc[2 * ra + 1]));
        const float* pv = pred + ((size_t)b * PP + p) * 25;
        float p0 = 1.f   / (1.f + expf(-pv[0]));
        float p1 = 1.f   / (1.f + expf(-pv[1]));
        float p2 = 0.5f  / (1.f + expf(-pv[2]));
        float p3 = 0.5f  / (1.f + expf(-pv[3]));
        float d0 = p0 - vx, d1 = p1 - vy, d2 = p2 - vw_, d3 = p3 - vh_;
        term = d0 * d0 + d1 * d1 + d2 * d2 + d3 * d3;
    }
    float cpart = (lane < NTILES) ? __ldcg(&g_confp[b * NTILES + lane]) : 0.f;
    #pragma unroll
    for (int o = 16; o; o >>= 1) {
        term  += __shfl_down_sync(0xFFFFFFFFu, term,  o);
        cpart += __shfl_down_sync(0xFFFFFFFFu, cpart, o);
    }

    int done = 0;
    if (lane == 0) {
        g_bctr[b] = 0;                 // reset for next launch
        g_bloc[b]  = (double)term;
        g_bconf[b] = (double)cpart;
        __threadfence();
        done = atomicAdd(&g_gctr, 1);
    }
    done = __shfl_sync(0xFFFFFFFFu, done, 0);
    if (done != BB - 1) return;

    // ===== global finalize (deterministic fixed-order reduce) =====
    double l = 0.0, c = 0.0;
    for (int i = lane; i < BB; i += 32) {
        l += __ldcg(&g_bloc[i]);
        c += __ldcg(&g_bconf[i]);
    }
    #pragma unroll
    for (int o = 16; o; o >>= 1) {
        l += __shfl_down_sync(0xFFFFFFFFu, l, o);
        c += __shfl_down_sync(0xFFFFFFFFu, c, o);
    }
    if (lane == 0) {
        double loc  = 5.0 * l / (double)BB;
        double conf = c / (double)BB;
        out[0] = (float)(loc + conf);
        out[1] = (float)loc;
        out[2] = (float)conf;
        g_gctr = 0;                    // reset for next launch
    }
}

extern "C" void kernel_launch(void* const* d_in, const int* in_sizes, int n_in,
                              void* d_out, int out_size)
{
    const float* pred = 0;
    const float* tgt  = 0;
    const float* anc  = 0;
    for (int i = 0; i < n_in; ++i) {
        if (in_sizes[i] == N_PRED)      pred = (const float*)d_in[i];
        else if (in_sizes[i] == N_TGT)  tgt  = (const float*)d_in[i];
        else if (in_sizes[i] == N_ANC)  anc  = (const float*)d_in[i];
    }
    float* out = (float*)d_out;

    k_main<<<BB * NTILES, TILE>>>(pred, tgt, anc, out);
}